// round 1
// baseline (speedup 1.0000x reference)
#include <cuda_runtime.h>
#include <cuda_bf16.h>
#include <math.h>

// Model constants
#define LAYERS 8
#define H      1024
#define NH     16
#define KVH    4
#define HD     64
#define INTER  2816
#define VOCAB  32000
#define CTX    2048
#define EPS    1e-5f

// scratch layout (floats)
#define O_H    0            // [1024] hidden state
#define O_X    1024         // [1024] normed
#define O_QKV  2048         // [1536] q(1024) k(256) v(256)
#define O_ATT  3584         // [1024]
#define O_GATE 4608         // [2816] silu(gate)
#define O_UP   7424         // [2816]
#define O_BVAL 10240        // [4000]
#define O_BIDX 14240        // [4000] (int bits)
#define NBLK   (VOCAB/8)    // 4000
#define SCR_SZ 18240

__device__ float g_scratch[SCR_SZ];

// ---------------------------------------------------------------------------
__global__ void embed_k(const float* __restrict__ embed,
                        const int* __restrict__ ids, float* __restrict__ S) {
    int tok = ids[0];
    S[O_H + threadIdx.x] = embed[(size_t)tok * H + threadIdx.x];
}

// ---------------------------------------------------------------------------
__global__ void rms_k(const float* __restrict__ h, const float* __restrict__ w,
                      float* __restrict__ x) {
    __shared__ float red[32];
    __shared__ float bs;
    int tid = threadIdx.x;
    float v = h[tid];
    float ss = v * v;
    #pragma unroll
    for (int o = 16; o; o >>= 1) ss += __shfl_xor_sync(~0u, ss, o);
    if ((tid & 31) == 0) red[tid >> 5] = ss;
    __syncthreads();
    if (tid == 0) {
        float t = 0.f;
        #pragma unroll
        for (int i = 0; i < 32; i++) t += red[i];
        bs = rsqrtf(t / (float)H + EPS);
    }
    __syncthreads();
    x[tid] = v * bs * w[tid];
}

// ---------------------------------------------------------------------------
__device__ __forceinline__ float warp_dot_1024(const float4* __restrict__ W,
                                               const float4* __restrict__ x4,
                                               int lane) {
    float s = 0.f;
    #pragma unroll
    for (int i = lane; i < H / 4; i += 32) {
        float4 w = W[i], a = x4[i];
        s += w.x * a.x + w.y * a.y + w.z * a.z + w.w * a.w;
    }
    #pragma unroll
    for (int o = 16; o; o >>= 1) s += __shfl_xor_sync(~0u, s, o);
    return s;
}

// fused q,k,v projections: rows 0..1023 q, 1024..1279 k, 1280..1535 v
__global__ void qkv_k(const float* __restrict__ qw, const float* __restrict__ kw,
                      const float* __restrict__ vw, float* __restrict__ S) {
    int wid = threadIdx.x >> 5, lane = threadIdx.x & 31;
    int row = blockIdx.x * 8 + wid;
    const float4* W;
    if (row < H)            W = (const float4*)(qw + (size_t)row * H);
    else if (row < H + 256) W = (const float4*)(kw + (size_t)(row - H) * H);
    else                    W = (const float4*)(vw + (size_t)(row - H - 256) * H);
    float s = warp_dot_1024(W, (const float4*)(S + O_X), lane);
    if (lane == 0) S[O_QKV + row] = s;
}

// ---------------------------------------------------------------------------
__global__ void rope_k(const float* __restrict__ cosc, const float* __restrict__ sinc,
                       const int* __restrict__ posp, float* __restrict__ S) {
    int tid = threadIdx.x;
    int pos = posp[0];
    int i = tid & (HD - 1);
    float c = cosc[(size_t)pos * HD + i];
    float s = sinc[(size_t)pos * HD + i];
    float q0 = S[O_QKV + tid];
    float qr = (i < HD / 2) ? -S[O_QKV + tid + HD / 2] : S[O_QKV + tid - HD / 2];
    float k0 = 0.f, kr = 0.f;
    if (tid < KVH * HD) {
        k0 = S[O_QKV + H + tid];
        kr = (i < HD / 2) ? -S[O_QKV + H + tid + HD / 2] : S[O_QKV + H + tid - HD / 2];
    }
    __syncthreads();
    S[O_QKV + tid] = q0 * c + qr * s;
    if (tid < KVH * HD) S[O_QKV + H + tid] = k0 * c + kr * s;
}

// ---------------------------------------------------------------------------
// One block per query head. Attends positions 0..pos; at j==pos uses new k/v.
__global__ void attn_k(const float* __restrict__ Kc, const float* __restrict__ Vc,
                       const int* __restrict__ posp, float* __restrict__ S) {
    __shared__ float sc[CTX];
    __shared__ float qs[HD];
    __shared__ float red[4];
    __shared__ float bM, bSum;
    int h = blockIdx.x, kvh = h >> 2, tid = threadIdx.x;
    int pos = posp[0];
    if (tid < HD) qs[tid] = S[O_QKV + h * HD + tid];
    __syncthreads();

    const float* K  = Kc + (size_t)kvh * CTX * HD;
    const float* kn = S + O_QKV + H + kvh * HD;
    for (int j = tid; j <= pos; j += blockDim.x) {
        const float* kr = (j == pos) ? kn : (K + (size_t)j * HD);
        float s = 0.f;
        #pragma unroll
        for (int d = 0; d < HD; d += 4) {
            s += qs[d] * kr[d] + qs[d+1] * kr[d+1] + qs[d+2] * kr[d+2] + qs[d+3] * kr[d+3];
        }
        sc[j] = s * 0.125f;  // 1/sqrt(64)
    }
    __syncthreads();

    // block max
    float m = -1e30f;
    for (int j = tid; j <= pos; j += blockDim.x) m = fmaxf(m, sc[j]);
    #pragma unroll
    for (int o = 16; o; o >>= 1) m = fmaxf(m, __shfl_xor_sync(~0u, m, o));
    if ((tid & 31) == 0) red[tid >> 5] = m;
    __syncthreads();
    if (tid == 0) {
        float t = red[0];
        for (int i = 1; i < 4; i++) t = fmaxf(t, red[i]);
        bM = t;
    }
    __syncthreads();
    float M = bM;

    float sum = 0.f;
    for (int j = tid; j <= pos; j += blockDim.x) {
        float e = expf(sc[j] - M);
        sc[j] = e;
        sum += e;
    }
    #pragma unroll
    for (int o = 16; o; o >>= 1) sum += __shfl_xor_sync(~0u, sum, o);
    if ((tid & 31) == 0) red[tid >> 5] = sum;
    __syncthreads();
    if (tid == 0) { bSum = red[0] + red[1] + red[2] + red[3]; }
    __syncthreads();
    float inv = 1.f / bSum;

    if (tid < HD) {
        const float* V = Vc + (size_t)kvh * CTX * HD;
        float acc = 0.f;
        int j = 0;
        for (; j + 4 <= pos; j += 4) {
            acc += sc[j]   * V[(size_t)j     * HD + tid];
            acc += sc[j+1] * V[(size_t)(j+1) * HD + tid];
            acc += sc[j+2] * V[(size_t)(j+2) * HD + tid];
            acc += sc[j+3] * V[(size_t)(j+3) * HD + tid];
        }
        for (; j < pos; j++) acc += sc[j] * V[(size_t)j * HD + tid];
        acc += sc[pos] * S[O_QKV + H + KVH * HD + kvh * HD + tid];
        S[O_ATT + h * HD + tid] = acc * inv;
    }
}

// ---------------------------------------------------------------------------
// generic matvec: y[row] = res[row] + dot(W[row,:], x .* x2)   (x2 optional)
__global__ void matvec_k(const float* __restrict__ W, const float* __restrict__ x,
                         const float* __restrict__ x2, const float* __restrict__ res,
                         float* __restrict__ y, int rows, int cols) {
    int wid = threadIdx.x >> 5, lane = threadIdx.x & 31;
    int row = blockIdx.x * 8 + wid;
    if (row >= rows) return;
    const float4* w4 = (const float4*)(W + (size_t)row * cols);
    const float4* a4 = (const float4*)x;
    const float4* b4 = (const float4*)x2;
    float s = 0.f;
    int n4 = cols >> 2;
    if (b4) {
        for (int i = lane; i < n4; i += 32) {
            float4 w = w4[i], a = a4[i], b = b4[i];
            s += w.x * (a.x * b.x) + w.y * (a.y * b.y) + w.z * (a.z * b.z) + w.w * (a.w * b.w);
        }
    } else {
        for (int i = lane; i < n4; i += 32) {
            float4 w = w4[i], a = a4[i];
            s += w.x * a.x + w.y * a.y + w.z * a.z + w.w * a.w;
        }
    }
    #pragma unroll
    for (int o = 16; o; o >>= 1) s += __shfl_xor_sync(~0u, s, o);
    if (lane == 0) y[row] = s + res[row];
}

// ---------------------------------------------------------------------------
// fused gate (with SiLU) + up projections; rows 0..2815 gate, 2816..5631 up
__global__ void gateup_k(const float* __restrict__ gw, const float* __restrict__ uw,
                         float* __restrict__ S) {
    int wid = threadIdx.x >> 5, lane = threadIdx.x & 31;
    int row = blockIdx.x * 8 + wid;
    bool is_gate = row < INTER;
    int r = is_gate ? row : row - INTER;
    const float4* W = (const float4*)((is_gate ? gw : uw) + (size_t)r * H);
    float s = warp_dot_1024(W, (const float4*)(S + O_X), lane);
    if (lane == 0) {
        if (is_gate) S[O_GATE + r] = s / (1.f + expf(-s));  // silu
        else         S[O_UP + r] = s;
    }
}

// ---------------------------------------------------------------------------
// lm_head matvec with per-block argmax (8 rows/block)
__global__ void lmhead_k(const float* __restrict__ W, const float* __restrict__ x,
                         float* __restrict__ bval, int* __restrict__ bidx) {
    __shared__ float sv[8];
    int wid = threadIdx.x >> 5, lane = threadIdx.x & 31;
    int row = blockIdx.x * 8 + wid;
    float s = warp_dot_1024((const float4*)(W + (size_t)row * H), (const float4*)x, lane);
    if (lane == 0) sv[wid] = s;
    __syncthreads();
    if (threadIdx.x == 0) {
        float b = sv[0]; int bi = 0;
        #pragma unroll
        for (int i = 1; i < 8; i++) if (sv[i] > b) { b = sv[i]; bi = i; }
        bval[blockIdx.x] = b;
        bidx[blockIdx.x] = blockIdx.x * 8 + bi;
    }
}

__global__ void argmax_k(const float* __restrict__ bval, const int* __restrict__ bidx,
                         float* __restrict__ out) {
    __shared__ float sv[1024];
    __shared__ int   si[1024];
    int tid = threadIdx.x;
    float b = -1e30f; int bi = 0x7fffffff;
    for (int i = tid; i < NBLK; i += 1024) {
        float v = bval[i]; int id = bidx[i];
        if (v > b || (v == b && id < bi)) { b = v; bi = id; }
    }
    sv[tid] = b; si[tid] = bi;
    __syncthreads();
    for (int s = 512; s; s >>= 1) {
        if (tid < s) {
            if (sv[tid + s] > sv[tid] || (sv[tid + s] == sv[tid] && si[tid + s] < si[tid])) {
                sv[tid] = sv[tid + s]; si[tid] = si[tid + s];
            }
        }
        __syncthreads();
    }
    if (tid == 0) { out[0] = (float)si[0]; out[1] = sv[0]; }
}

// ---------------------------------------------------------------------------
extern "C" void kernel_launch(void* const* d_in, const int* in_sizes, int n_in,
                              void* d_out, int out_size) {
    const float* embed   = (const float*)d_in[0];
    const float* q_w     = (const float*)d_in[1];
    const float* k_w     = (const float*)d_in[2];
    const float* v_w     = (const float*)d_in[3];
    const float* o_w     = (const float*)d_in[4];
    const float* gate_w  = (const float*)d_in[5];
    const float* up_w    = (const float*)d_in[6];
    const float* down_w  = (const float*)d_in[7];
    const float* ln1_w   = (const float*)d_in[8];
    const float* ln2_w   = (const float*)d_in[9];
    const float* norm_w  = (const float*)d_in[10];
    const float* lm_head = (const float*)d_in[11];
    const float* kv      = (const float*)d_in[12];
    const float* cosc    = (const float*)d_in[13];
    const float* sinc    = (const float*)d_in[14];
    // d_in[15] causal_mask, d_in[16] update_mask — implied by position_ids
    const int* input_ids = (const int*)d_in[17];
    const int* pos_ids   = (const int*)d_in[18];

    float* S;
    cudaGetSymbolAddress((void**)&S, g_scratch);

    embed_k<<<1, H>>>(embed, input_ids, S);

    for (int l = 0; l < LAYERS; l++) {
        const float* Kc = kv + (size_t)l * KVH * CTX * HD;
        const float* Vc = kv + (size_t)(LAYERS + l) * KVH * CTX * HD;

        rms_k<<<1, H>>>(S + O_H, ln1_w + (size_t)l * H, S + O_X);
        qkv_k<<<(H + 2 * KVH * HD) / 8, 256>>>(q_w + (size_t)l * H * H,
                                               k_w + (size_t)l * KVH * HD * H,
                                               v_w + (size_t)l * KVH * HD * H, S);
        rope_k<<<1, H>>>(cosc, sinc, pos_ids, S);
        attn_k<<<NH, 128>>>(Kc, Vc, pos_ids, S);
        matvec_k<<<H / 8, 256>>>(o_w + (size_t)l * H * H, S + O_ATT, nullptr,
                                 S + O_H, S + O_H, H, H);
        rms_k<<<1, H>>>(S + O_H, ln2_w + (size_t)l * H, S + O_X);
        gateup_k<<<(2 * INTER) / 8, 256>>>(gate_w + (size_t)l * INTER * H,
                                           up_w + (size_t)l * INTER * H, S);
        matvec_k<<<H / 8, 256>>>(down_w + (size_t)l * H * INTER, S + O_GATE,
                                 S + O_UP, S + O_H, S + O_H, H, INTER);
    }

    rms_k<<<1, H>>>(S + O_H, norm_w, S + O_X);
    lmhead_k<<<NBLK, 256>>>(lm_head, S + O_X, S + O_BVAL, (int*)(S + O_BIDX));
    argmax_k<<<1, 1024>>>(S + O_BVAL, (int*)(S + O_BIDX), (float*)d_out);
}

// round 2
// speedup vs baseline: 3.2865x; 3.2865x over previous
#include <cuda_runtime.h>
#include <math.h>

#define LAYERS 8
#define H      1024
#define NH     16
#define KVH    4
#define HD     64
#define INTER  2816
#define VOCAB  32000
#define CTX    2048
#define EPS    1e-5f

#define NBLOCKS 148
#define NWARPS  (NBLOCKS * 32)

// ---------------------------------------------------------------------------
// global scratch (allocation-free)
__device__ __align__(16) float g_h[H];
__device__ __align__(16) float g_qkv[H + 2 * KVH * HD];   // q(1024) k(256) v(256)
__device__ __align__(16) float g_att[H];
__device__ __align__(16) float g_gact[INTER];
__device__ float    g_lmv[NBLOCKS];
__device__ int      g_lmi[NBLOCKS];
__device__ unsigned g_barcnt;
__device__ unsigned g_bargen;

// ---------------------------------------------------------------------------
__device__ __forceinline__ void grid_sync() {
    __syncthreads();
    if (threadIdx.x == 0) {
        __threadfence();  // release: publish writes, invalidate L1
        unsigned gen = *(volatile unsigned*)&g_bargen;
        if (atomicAdd(&g_barcnt, 1u) == NBLOCKS - 1) {
            g_barcnt = 0;
            __threadfence();
            atomicAdd(&g_bargen, 1u);
        } else {
            while (*(volatile unsigned*)&g_bargen == gen) { }
            __threadfence();  // acquire: invalidate L1 before consuming
        }
    }
    __syncthreads();
}

// warp dot: W (global) x (smem or global), n4 = cols/4
__device__ __forceinline__ float wdot(const float* __restrict__ W,
                                      const float* __restrict__ x,
                                      int n4, int lane) {
    const float4* w4 = (const float4*)W;
    const float4* x4 = (const float4*)x;
    float s = 0.f;
    #pragma unroll 8
    for (int i = lane; i < n4; i += 32) {
        float4 w = w4[i], a = x4[i];
        s += w.x * a.x + w.y * a.y + w.z * a.z + w.w * a.w;
    }
    #pragma unroll
    for (int o = 16; o; o >>= 1) s += __shfl_xor_sync(~0u, s, o);
    return s;
}

// block sum over 1024 threads
__device__ __forceinline__ float block_rsum(float v, float* red) {
    int lane = threadIdx.x & 31, wid = threadIdx.x >> 5;
    #pragma unroll
    for (int o = 16; o; o >>= 1) v += __shfl_xor_sync(~0u, v, o);
    if (lane == 0) red[wid] = v;
    __syncthreads();
    if (threadIdx.x == 0) {
        float t = 0.f;
        #pragma unroll
        for (int i = 0; i < 32; i++) t += red[i];
        red[0] = t;
    }
    __syncthreads();
    float r = red[0];
    __syncthreads();
    return r;
}

// ---------------------------------------------------------------------------
__global__ void __launch_bounds__(1024, 1)
decode_k(const float* __restrict__ embed,  const float* __restrict__ q_w,
         const float* __restrict__ k_w,    const float* __restrict__ v_w,
         const float* __restrict__ o_w,    const float* __restrict__ gate_w,
         const float* __restrict__ up_w,   const float* __restrict__ down_w,
         const float* __restrict__ ln1_w,  const float* __restrict__ ln2_w,
         const float* __restrict__ norm_w, const float* __restrict__ lm_head,
         const float* __restrict__ kv,     const float* __restrict__ cosc,
         const float* __restrict__ sinc,   const int* __restrict__ input_ids,
         const int* __restrict__ pos_ids,  float* __restrict__ out) {
    __shared__ __align__(16) float xs[H];
    __shared__ float red[32];
    __shared__ int   redi[32];
    __shared__ __align__(16) float sc[CTX];
    __shared__ __align__(16) float part[32][HD];
    __shared__ __align__(16) float qs[HD];
    __shared__ __align__(16) float kn[HD];
    __shared__ __align__(16) float vn[HD];

    const int tid = threadIdx.x, lane = tid & 31, wid = tid >> 5;
    const int gw = blockIdx.x * 32 + wid;

    // embedding
    if (blockIdx.x == 0) {
        int tok = input_ids[0];
        g_h[tid] = embed[(size_t)tok * H + tid];
    }
    grid_sync();

    const int pos = pos_ids[0];

    for (int l = 0; l < LAYERS; l++) {
        // ---- rms1 folded: xs = h * ln1_w, rs computed per block ----
        float hv = g_h[tid];
        xs[tid] = hv * ln1_w[(size_t)l * H + tid];
        float ssq = block_rsum(hv * hv, red);
        float rs = rsqrtf(ssq / (float)H + EPS);

        // ---- qkv: 1536 rows, warp-per-row ----
        if (gw < H + 2 * KVH * HD) {
            const float* W;
            if (gw < H)
                W = q_w + (size_t)l * H * H + (size_t)gw * H;
            else if (gw < H + KVH * HD)
                W = k_w + (size_t)l * KVH * HD * H + (size_t)(gw - H) * H;
            else
                W = v_w + (size_t)l * KVH * HD * H + (size_t)(gw - H - KVH * HD) * H;
            float s = wdot(W, xs, H / 4, lane) * rs;
            if (lane == 0) g_qkv[gw] = s;
        }
        grid_sync();

        // ---- attention: block b < 16 handles head b (rope applied locally) ----
        if (blockIdx.x < NH) {
            int hh = blockIdx.x, kvh = hh >> 2;
            if (tid < HD) {
                float c  = cosc[(size_t)pos * HD + tid];
                float sn = sinc[(size_t)pos * HD + tid];
                float q0 = g_qkv[hh * HD + tid];
                float qr = (tid < HD / 2) ? -g_qkv[hh * HD + tid + HD / 2]
                                          :  g_qkv[hh * HD + tid - HD / 2];
                qs[tid] = q0 * c + qr * sn;
                float k0 = g_qkv[H + kvh * HD + tid];
                float kr = (tid < HD / 2) ? -g_qkv[H + kvh * HD + tid + HD / 2]
                                          :  g_qkv[H + kvh * HD + tid - HD / 2];
                kn[tid] = k0 * c + kr * sn;
                vn[tid] = g_qkv[H + KVH * HD + kvh * HD + tid];
            }
            __syncthreads();

            const float* K = kv + (size_t)l * KVH * CTX * HD + (size_t)kvh * CTX * HD;
            const float* V = kv + (size_t)(LAYERS + l) * KVH * CTX * HD + (size_t)kvh * CTX * HD;

            for (int j = tid; j <= pos; j += 1024) {
                const float* kr = (j == pos) ? (const float*)kn : K + (size_t)j * HD;
                const float4* k4 = (const float4*)kr;
                const float4* q4 = (const float4*)qs;
                float s = 0.f;
                #pragma unroll
                for (int d = 0; d < HD / 4; d++) {
                    float4 a = q4[d], b = k4[d];
                    s += a.x * b.x + a.y * b.y + a.z * b.z + a.w * b.w;
                }
                sc[j] = s * 0.125f;
            }
            __syncthreads();

            // block max
            float m = -1e30f;
            for (int j = tid; j <= pos; j += 1024) m = fmaxf(m, sc[j]);
            #pragma unroll
            for (int o = 16; o; o >>= 1) m = fmaxf(m, __shfl_xor_sync(~0u, m, o));
            if (lane == 0) red[wid] = m;
            __syncthreads();
            if (tid == 0) {
                float t = red[0];
                #pragma unroll
                for (int i = 1; i < 32; i++) t = fmaxf(t, red[i]);
                red[0] = t;
            }
            __syncthreads();
            float M = red[0];
            __syncthreads();

            float sum = 0.f;
            for (int j = tid; j <= pos; j += 1024) {
                float e = __expf(sc[j] - M);
                sc[j] = e;
                sum += e;
            }
            float S = block_rsum(sum, red);
            float inv = 1.f / S;

            // AV: warps chunk positions, lanes own 2 dims
            int npos = pos + 1;
            int chunk = (npos + 31) >> 5;
            int j0 = wid * chunk;
            int j1 = min(j0 + chunk, npos);
            float a0 = 0.f, a1 = 0.f;
            for (int j = j0; j < j1; j++) {
                float p = sc[j];
                const float* Vr = (j == pos) ? (const float*)vn : V + (size_t)j * HD;
                a0 += p * Vr[lane];
                a1 += p * Vr[lane + 32];
            }
            part[wid][lane]      = a0;
            part[wid][lane + 32] = a1;
            __syncthreads();
            if (tid < HD) {
                float t = 0.f;
                #pragma unroll
                for (int w = 0; w < 32; w++) t += part[w][tid];
                g_att[hh * HD + tid] = t * inv;
            }
        }
        grid_sync();

        // ---- o-proj + residual ----
        xs[tid] = g_att[tid];
        __syncthreads();
        if (gw < H) {
            const float* W = o_w + (size_t)l * H * H + (size_t)gw * H;
            float s = wdot(W, xs, H / 4, lane);
            if (lane == 0) g_h[gw] += s;
        }
        grid_sync();

        // ---- rms2 folded ----
        hv = g_h[tid];
        xs[tid] = hv * ln2_w[(size_t)l * H + tid];
        ssq = block_rsum(hv * hv, red);
        rs = rsqrtf(ssq / (float)H + EPS);

        // ---- gate+up fused, interleaved loads ----
        if (gw < INTER) {
            const float4* Wg = (const float4*)(gate_w + (size_t)l * INTER * H + (size_t)gw * H);
            const float4* Wu = (const float4*)(up_w   + (size_t)l * INTER * H + (size_t)gw * H);
            const float4* x4 = (const float4*)xs;
            float sg = 0.f, su = 0.f;
            #pragma unroll 8
            for (int i = lane; i < H / 4; i += 32) {
                float4 wg = Wg[i], wu = Wu[i], a = x4[i];
                sg += wg.x * a.x + wg.y * a.y + wg.z * a.z + wg.w * a.w;
                su += wu.x * a.x + wu.y * a.y + wu.z * a.z + wu.w * a.w;
            }
            #pragma unroll
            for (int o = 16; o; o >>= 1) {
                sg += __shfl_xor_sync(~0u, sg, o);
                su += __shfl_xor_sync(~0u, su, o);
            }
            if (lane == 0) {
                float g = sg * rs, u = su * rs;
                g_gact[gw] = (g / (1.f + __expf(-g))) * u;
            }
        }
        grid_sync();

        // ---- down-proj + residual ----
        if (gw < H) {
            const float* W = down_w + (size_t)l * H * INTER + (size_t)gw * INTER;
            float s = wdot(W, g_gact, INTER / 4, lane);
            if (lane == 0) g_h[gw] += s;
        }
        grid_sync();
    }

    // ---- final norm (folded) + lm_head + argmax ----
    float hv = g_h[tid];
    xs[tid] = hv * norm_w[tid];
    float ssq = block_rsum(hv * hv, red);
    float rsf = rsqrtf(ssq / (float)H + EPS);

    float bv = -1e30f;
    int   bi = 0;
    for (int r = gw; r < VOCAB; r += NWARPS) {
        float s = wdot(lm_head + (size_t)r * H, xs, H / 4, lane) * rsf;
        if (s > bv) { bv = s; bi = r; }
    }
    if (lane == 0) { red[wid] = bv; redi[wid] = bi; }
    __syncthreads();
    if (tid == 0) {
        float b = red[0]; int ii = redi[0];
        #pragma unroll
        for (int i = 1; i < 32; i++) {
            if (red[i] > b || (red[i] == b && redi[i] < ii)) { b = red[i]; ii = redi[i]; }
        }
        g_lmv[blockIdx.x] = b;
        g_lmi[blockIdx.x] = ii;
    }
    grid_sync();
    if (blockIdx.x == 0 && tid == 0) {
        float b = g_lmv[0]; int ii = g_lmi[0];
        for (int i = 1; i < NBLOCKS; i++) {
            float v = g_lmv[i]; int id = g_lmi[i];
            if (v > b || (v == b && id < ii)) { b = v; ii = id; }
        }
        out[0] = (float)ii;
        out[1] = b;
    }
}

// ---------------------------------------------------------------------------
extern "C" void kernel_launch(void* const* d_in, const int* in_sizes, int n_in,
                              void* d_out, int out_size) {
    const float* embed   = (const float*)d_in[0];
    const float* q_w     = (const float*)d_in[1];
    const float* k_w     = (const float*)d_in[2];
    const float* v_w     = (const float*)d_in[3];
    const float* o_w     = (const float*)d_in[4];
    const float* gate_w  = (const float*)d_in[5];
    const float* up_w    = (const float*)d_in[6];
    const float* down_w  = (const float*)d_in[7];
    const float* ln1_w   = (const float*)d_in[8];
    const float* ln2_w   = (const float*)d_in[9];
    const float* norm_w  = (const float*)d_in[10];
    const float* lm_head = (const float*)d_in[11];
    const float* kv      = (const float*)d_in[12];
    const float* cosc    = (const float*)d_in[13];
    const float* sinc    = (const float*)d_in[14];
    // d_in[15] causal_mask, d_in[16] update_mask: implied by position_ids
    const int* input_ids = (const int*)d_in[17];
    const int* pos_ids   = (const int*)d_in[18];

    decode_k<<<NBLOCKS, 1024>>>(embed, q_w, k_w, v_w, o_w, gate_w, up_w, down_w,
                                ln1_w, ln2_w, norm_w, lm_head, kv, cosc, sinc,
                                input_ids, pos_ids, (float*)d_out);
}

// round 4
// speedup vs baseline: 4.6423x; 1.4126x over previous
#include <cuda_runtime.h>
#include <math.h>

#define LAYERS 8
#define H      1024
#define NH     16
#define KVH    4
#define HD     64
#define INTER  2816
#define VOCAB  32000
#define CTX    2048
#define EPS    1e-5f

#define NBLOCKS 148
#define NWARPS  (NBLOCKS * 32)
#define ACHUNKS 8           // attention position chunks per head

// ---------------------------------------------------------------------------
// global scratch (allocation-free)
__device__ __align__(16) float g_hA[H];
__device__ __align__(16) float g_hB[H];
__device__ __align__(16) float g_qkvp[2][H + 2 * KVH * HD];   // qkv split-2 partials
__device__ __align__(16) float g_op[4][H];                    // o-proj partials
__device__ __align__(16) float g_gp[2][INTER];                // gate partials
__device__ __align__(16) float g_upp[2][INTER];               // up partials
__device__ __align__(16) float g_dp[4][H];                    // down partials
__device__ float g_am[NH][ACHUNKS];                           // chunk max
__device__ float g_as[NH][ACHUNKS];                           // chunk expsum
__device__ __align__(16) float g_ao[NH][ACHUNKS][HD];         // chunk sum(e*v)
__device__ float    g_lmv[NBLOCKS];
__device__ int      g_lmi[NBLOCKS];
__device__ unsigned g_barcnt;
__device__ unsigned g_bargen;

// ---------------------------------------------------------------------------
__device__ __forceinline__ void grid_sync() {
    __syncthreads();
    if (threadIdx.x == 0) {
        __threadfence();
        unsigned gen = *(volatile unsigned*)&g_bargen;
        if (atomicAdd(&g_barcnt, 1u) == NBLOCKS - 1) {
            g_barcnt = 0;
            __threadfence();
            atomicAdd(&g_bargen, 1u);
        } else {
            while (*(volatile unsigned*)&g_bargen == gen) { }
            __threadfence();
        }
    }
    __syncthreads();
}

// block sum over 1024 threads (returns to all threads)
__device__ __forceinline__ float block_rsum(float v, float* red) {
    int lane = threadIdx.x & 31, wid = threadIdx.x >> 5;
    #pragma unroll
    for (int o = 16; o; o >>= 1) v += __shfl_xor_sync(~0u, v, o);
    if (lane == 0) red[wid] = v;
    __syncthreads();
    if (threadIdx.x == 0) {
        float t = 0.f;
        #pragma unroll
        for (int i = 0; i < 32; i++) t += red[i];
        red[0] = t;
    }
    __syncthreads();
    float r = red[0];
    __syncthreads();
    return r;
}

__device__ __forceinline__ float block_rmax(float v, float* red) {
    int lane = threadIdx.x & 31, wid = threadIdx.x >> 5;
    #pragma unroll
    for (int o = 16; o; o >>= 1) v = fmaxf(v, __shfl_xor_sync(~0u, v, o));
    if (lane == 0) red[wid] = v;
    __syncthreads();
    if (threadIdx.x == 0) {
        float t = red[0];
        #pragma unroll
        for (int i = 1; i < 32; i++) t = fmaxf(t, red[i]);
        red[0] = t;
    }
    __syncthreads();
    float r = red[0];
    __syncthreads();
    return r;
}

// ---------------------------------------------------------------------------
__global__ void __launch_bounds__(1024, 1)
decode_k(const float* __restrict__ embed,  const float* __restrict__ q_w,
         const float* __restrict__ k_w,    const float* __restrict__ v_w,
         const float* __restrict__ o_w,    const float* __restrict__ gate_w,
         const float* __restrict__ up_w,   const float* __restrict__ down_w,
         const float* __restrict__ ln1_w,  const float* __restrict__ ln2_w,
         const float* __restrict__ norm_w, const float* __restrict__ lm_head,
         const float* __restrict__ kv,     const float* __restrict__ cosc,
         const float* __restrict__ sinc,   const int* __restrict__ input_ids,
         const int* __restrict__ pos_ids,  float* __restrict__ out) {
    __shared__ __align__(16) float xs[H];       // normed hidden / att operand
    __shared__ __align__(16) float xm[INTER];   // MLP activation operand
    __shared__ __align__(16) float sc[256];     // attention chunk scores
    __shared__ __align__(16) float part[32][HD];
    __shared__ __align__(16) float qs[HD], kn[HD], vn[HD];
    __shared__ float red[32];
    __shared__ int   redi[32];

    const int tid = threadIdx.x, lane = tid & 31, wid = tid >> 5;
    const int bid = blockIdx.x;
    const int gwarp = bid * 32 + wid;

    // ---- embed + zero first-layer down partials ----
    if (bid == 0) g_hA[tid] = embed[(size_t)input_ids[0] * H + tid];
    if (bid == 1) {
        #pragma unroll
        for (int s = 0; s < 4; s++) g_dp[s][tid] = 0.f;
    }
    grid_sync();

    const int pos = pos_ids[0];
    const int cl = (pos + ACHUNKS) >> 3;   // ceil((pos+1)/8)

    for (int l = 0; l < LAYERS; l++) {
        // =========== S1: combine h, rms1, qkv partials ===========
        float hv = g_hA[tid] + g_dp[0][tid] + g_dp[1][tid] + g_dp[2][tid] + g_dp[3][tid];
        if (bid == 0) g_hB[tid] = hv;
        xs[tid] = hv * ln1_w[(size_t)l * H + tid];
        float ssq = block_rsum(hv * hv, red);
        float rs = rsqrtf(ssq / (float)H + EPS);

        if (gwarp < 2 * (H + 2 * KVH * HD)) {           // 3072 units
            int row = gwarp >> 1, s2 = gwarp & 1;
            const float* W;
            if (row < H)
                W = q_w + (size_t)l * H * H + (size_t)row * H;
            else if (row < H + KVH * HD)
                W = k_w + (size_t)l * (KVH * HD) * H + (size_t)(row - H) * H;
            else
                W = v_w + (size_t)l * (KVH * HD) * H + (size_t)(row - H - KVH * HD) * H;
            const float4* w4 = (const float4*)W;
            const float4* x4 = (const float4*)xs;
            float s = 0.f;
            #pragma unroll
            for (int k = 0; k < 4; k++) {
                int i = s2 * 128 + lane + k * 32;
                float4 w = w4[i], a = x4[i];
                s += w.x * a.x + w.y * a.y + w.z * a.z + w.w * a.w;
            }
            #pragma unroll
            for (int o = 16; o; o >>= 1) s += __shfl_xor_sync(~0u, s, o);
            if (lane == 0) g_qkvp[s2][row] = s * rs;
        }
        grid_sync();

        // =========== S2: attention (flash-decode, 128 blocks) ===========
        if (bid < NH * ACHUNKS) {
            int head = bid >> 3, ch = bid & (ACHUNKS - 1), kvh = head >> 2;
            int j0 = ch * cl;
            int j1 = min(j0 + cl, pos + 1);
            int n = j1 - j0;

            if (tid < HD) {
                float c  = cosc[(size_t)pos * HD + tid];
                float sn = sinc[(size_t)pos * HD + tid];
                int qi = head * HD + tid;
                float q0 = g_qkvp[0][qi] + g_qkvp[1][qi];
                int qr_i = head * HD + ((tid < HD / 2) ? tid + HD / 2 : tid - HD / 2);
                float qr = g_qkvp[0][qr_i] + g_qkvp[1][qr_i];
                if (tid < HD / 2) qr = -qr;
                qs[tid] = q0 * c + qr * sn;

                int ki = H + kvh * HD + tid;
                float k0 = g_qkvp[0][ki] + g_qkvp[1][ki];
                int kr_i = H + kvh * HD + ((tid < HD / 2) ? tid + HD / 2 : tid - HD / 2);
                float kr = g_qkvp[0][kr_i] + g_qkvp[1][kr_i];
                if (tid < HD / 2) kr = -kr;
                kn[tid] = k0 * c + kr * sn;

                int vi = H + KVH * HD + kvh * HD + tid;
                vn[tid] = g_qkvp[0][vi] + g_qkvp[1][vi];
            }
            __syncthreads();

            const float* K = kv + (size_t)l * KVH * CTX * HD + (size_t)kvh * CTX * HD;
            const float* V = kv + (size_t)(LAYERS + l) * KVH * CTX * HD + (size_t)kvh * CTX * HD;
            const float4* q4 = (const float4*)qs;

            // scores: half-warp per row (coalesced). WARP-UNIFORM loop bound:
            // all 32 lanes iterate together; the odd tail row is predicated so
            // the full-mask shfl below always has every lane present.
            int half = lane >> 4, hl = lane & 15;
            for (int jb = j0 + wid * 2; jb < j1; jb += 64) {
                int j = jb + half;
                bool valid = (j < j1);
                const float4* k4;
                if (!valid)           k4 = (const float4*)kn;   // safe dummy
                else if (j == pos)    k4 = (const float4*)kn;
                else                  k4 = (const float4*)(K + (size_t)j * HD);
                float4 a = q4[hl], b = k4[hl];
                float s = a.x * b.x + a.y * b.y + a.z * b.z + a.w * b.w;
                #pragma unroll
                for (int o = 8; o; o >>= 1) s += __shfl_xor_sync(~0u, s, o);
                if (hl == 0 && valid) sc[j - j0] = s * 0.125f;
            }
            __syncthreads();

            float m = -1e30f;
            if (tid < n) m = sc[tid];      // n <= cl <= 256
            float M = block_rmax(m, red);

            float e = 0.f;
            if (tid < n) {
                e = __expf(sc[tid] - M);
                sc[tid] = e;
            }
            float S = block_rsum(e, red);

            // AV: warps stride positions, lanes own 2 dims (no shfl inside)
            float a0 = 0.f, a1 = 0.f;
            for (int j = j0 + wid; j < j1; j += 32) {
                float p = sc[j - j0];
                const float* Vr = (j == pos) ? (const float*)vn : V + (size_t)j * HD;
                a0 += p * Vr[lane];
                a1 += p * Vr[lane + 32];
            }
            part[wid][lane]      = a0;
            part[wid][lane + 32] = a1;
            __syncthreads();
            if (tid == 0) { g_am[head][ch] = (n > 0) ? M : -1e30f; g_as[head][ch] = S; }
            if (tid < HD) {
                float t = 0.f;
                #pragma unroll
                for (int w = 0; w < 32; w++) t += part[w][tid];
                g_ao[head][ch][tid] = t;
            }
        }
        grid_sync();

        // =========== S3: combine attention, o-proj partials ===========
        {
            int head = tid >> 6, d = tid & (HD - 1);
            float M = -1e30f;
            #pragma unroll
            for (int c = 0; c < ACHUNKS; c++) M = fmaxf(M, g_am[head][c]);
            float S = 0.f, o = 0.f;
            #pragma unroll
            for (int c = 0; c < ACHUNKS; c++) {
                float e = __expf(g_am[head][c] - M);
                S += g_as[head][c] * e;
                o += g_ao[head][c][d] * e;
            }
            xs[tid] = o / S;
        }
        __syncthreads();

        if (gwarp < 4 * H) {                            // 4096 units
            int row = gwarp >> 2, s4 = gwarp & 3;
            const float4* w4 = (const float4*)(o_w + (size_t)l * H * H + (size_t)row * H);
            const float4* x4 = (const float4*)xs;
            float s = 0.f;
            #pragma unroll
            for (int k = 0; k < 2; k++) {
                int i = s4 * 64 + lane + k * 32;
                float4 w = w4[i], a = x4[i];
                s += w.x * a.x + w.y * a.y + w.z * a.z + w.w * a.w;
            }
            #pragma unroll
            for (int o = 16; o; o >>= 1) s += __shfl_xor_sync(~0u, s, o);
            if (lane == 0) g_op[s4][row] = s;
        }
        grid_sync();

        // =========== S4: combine h, rms2, gate+up partials ===========
        hv = g_hB[tid] + g_op[0][tid] + g_op[1][tid] + g_op[2][tid] + g_op[3][tid];
        if (bid == 0) g_hA[tid] = hv;
        xs[tid] = hv * ln2_w[(size_t)l * H + tid];
        ssq = block_rsum(hv * hv, red);
        rs = rsqrtf(ssq / (float)H + EPS);

        for (int u = gwarp; u < 2 * INTER; u += NWARPS) {   // 5632 units
            int r = u >> 1, s2 = u & 1;
            const float4* Wg = (const float4*)(gate_w + (size_t)l * INTER * H + (size_t)r * H);
            const float4* Wu = (const float4*)(up_w   + (size_t)l * INTER * H + (size_t)r * H);
            const float4* x4 = (const float4*)xs;
            float sg = 0.f, su = 0.f;
            #pragma unroll
            for (int k = 0; k < 4; k++) {
                int i = s2 * 128 + lane + k * 32;
                float4 wg = Wg[i], wu = Wu[i], a = x4[i];
                sg += wg.x * a.x + wg.y * a.y + wg.z * a.z + wg.w * a.w;
                su += wu.x * a.x + wu.y * a.y + wu.z * a.z + wu.w * a.w;
            }
            #pragma unroll
            for (int o = 16; o; o >>= 1) {
                sg += __shfl_xor_sync(~0u, sg, o);
                su += __shfl_xor_sync(~0u, su, o);
            }
            if (lane == 0) { g_gp[s2][r] = sg * rs; g_upp[s2][r] = su * rs; }
        }
        grid_sync();

        // =========== S5: combine gact -> smem, down partials ===========
        for (int i = tid; i < INTER; i += 1024) {
            float g = g_gp[0][i] + g_gp[1][i];
            float u = g_upp[0][i] + g_upp[1][i];
            xm[i] = (g / (1.f + __expf(-g))) * u;
        }
        __syncthreads();

        if (gwarp < 4 * H) {                            // 4096 units, 704 cols each
            int row = gwarp >> 2, s4 = gwarp & 3;
            const float4* w4 = (const float4*)(down_w + (size_t)l * H * INTER
                                               + (size_t)row * INTER + (size_t)s4 * 704);
            const float4* x4 = (const float4*)(xm + s4 * 704);
            float s = 0.f;
            for (int i = lane; i < 176; i += 32) {
                float4 w = w4[i], a = x4[i];
                s += w.x * a.x + w.y * a.y + w.z * a.z + w.w * a.w;
            }
            #pragma unroll
            for (int o = 16; o; o >>= 1) s += __shfl_xor_sync(~0u, s, o);
            if (lane == 0) g_dp[s4][row] = s;
        }
        grid_sync();
    }

    // =========== final norm + lm_head + argmax ===========
    float hv = g_hA[tid] + g_dp[0][tid] + g_dp[1][tid] + g_dp[2][tid] + g_dp[3][tid];
    xs[tid] = hv * norm_w[tid];
    float ssq = block_rsum(hv * hv, red);
    float rsf = rsqrtf(ssq / (float)H + EPS);

    float bv = -1e30f;
    int   bi = 0x7fffffff;
    for (int r = gwarp; r < VOCAB; r += NWARPS) {
        const float4* w4 = (const float4*)(lm_head + (size_t)r * H);
        const float4* x4 = (const float4*)xs;
        float s = 0.f;
        #pragma unroll
        for (int k = 0; k < 8; k++) {
            int i = lane + k * 32;
            float4 w = w4[i], a = x4[i];
            s += w.x * a.x + w.y * a.y + w.z * a.z + w.w * a.w;
        }
        #pragma unroll
        for (int o = 16; o; o >>= 1) s += __shfl_xor_sync(~0u, s, o);
        s *= rsf;
        if (s > bv) { bv = s; bi = r; }
    }
    if (lane == 0) { red[wid] = bv; redi[wid] = bi; }
    __syncthreads();
    if (tid == 0) {
        float b = red[0]; int ii = redi[0];
        #pragma unroll
        for (int i = 1; i < 32; i++)
            if (red[i] > b || (red[i] == b && redi[i] < ii)) { b = red[i]; ii = redi[i]; }
        g_lmv[bid] = b;
        g_lmi[bid] = ii;
    }
    grid_sync();
    if (bid == 0 && tid == 0) {
        float b = g_lmv[0]; int ii = g_lmi[0];
        for (int i = 1; i < NBLOCKS; i++) {
            float v = g_lmv[i]; int id = g_lmi[i];
            if (v > b || (v == b && id < ii)) { b = v; ii = id; }
        }
        out[0] = (float)ii;
        out[1] = b;
    }
}

// ---------------------------------------------------------------------------
extern "C" void kernel_launch(void* const* d_in, const int* in_sizes, int n_in,
                              void* d_out, int out_size) {
    const float* embed   = (const float*)d_in[0];
    const float* q_w     = (const float*)d_in[1];
    const float* k_w     = (const float*)d_in[2];
    const float* v_w     = (const float*)d_in[3];
    const float* o_w     = (const float*)d_in[4];
    const float* gate_w  = (const float*)d_in[5];
    const float* up_w    = (const float*)d_in[6];
    const float* down_w  = (const float*)d_in[7];
    const float* ln1_w   = (const float*)d_in[8];
    const float* ln2_w   = (const float*)d_in[9];
    const float* norm_w  = (const float*)d_in[10];
    const float* lm_head = (const float*)d_in[11];
    const float* kv      = (const float*)d_in[12];
    const float* cosc    = (const float*)d_in[13];
    const float* sinc    = (const float*)d_in[14];
    const int* input_ids = (const int*)d_in[17];
    const int* pos_ids   = (const int*)d_in[18];

    decode_k<<<NBLOCKS, 1024>>>(embed, q_w, k_w, v_w, o_w, gate_w, up_w, down_w,
                                ln1_w, ln2_w, norm_w, lm_head, kv, cosc, sinc,
                                input_ids, pos_ids, (float*)d_out);
}